// round 6
// baseline (speedup 1.0000x reference)
#include <cuda_runtime.h>
#include <cstdint>
#include <cstddef>

// out[t,e,o] = sum_r x[t, e*128+r] * W[e,o,r]
// x: [8192, 1024] f32, W: [8, 4096, 128] f32, out: [8192, 8, 4096] f32
//
// mma.sync TF32 (legacy tensor path; tcgen05 is unavailable: harness compiles
// via compute_103 PTX which rejects 'a'-suffix features).
//
// Grid = 16 N-tiles(256) x 8 experts = 128 persistent CTAs (1 wave on 148 SMs).
// Per CTA: W[256x128] tf32-rounded resident in SMEM (128KB, loaded once).
// X streamed per 128-row M-iter in two 64-wide K chunks through a 2x32KB
// double buffer by 2 producer warps (LDG -> cvt.rna.tf32 -> swizzled STS),
// mbarrier-synchronized with 8 compute warps (warp tile 64x64 -> 1.0 LDS/MMA).

#define EXPERTS  8
#define RANK     128
#define OUTF     4096
#define BM       128
#define BN       256
#define NTHREADS 320          // 8 compute warps + 2 producer warps

// SMEM layout (bytes)
#define SM_FULL0   0          // mbar: chunk buf0 full   (count 64)
#define SM_FULL1   8
#define SM_FREE0   16         // mbar: chunk buf0 free   (count 256)
#define SM_FREE1   24
#define SM_X       1024       // 2 x 32768: [128 rows][64 tf32] swizzled
#define SM_W       (1024 + 65536)       // 256 rows x 128 tf32 swizzled = 128KB
#define SMEM_TOTAL (SM_W + 131072)      // 197632

__device__ __forceinline__ uint32_t smem_u32(const void* p) {
    uint32_t a;
    asm("{ .reg .u64 t; cvta.to.shared.u64 t, %1; cvt.u32.u64 %0, t; }" : "=r"(a) : "l"(p));
    return a;
}
__device__ __forceinline__ uint32_t tf32u(float f) {
    uint32_t u;
    asm("cvt.rna.tf32.f32 %0, %1;" : "=r"(u) : "f"(f));
    return u;
}
__device__ __forceinline__ void mbar_init(uint32_t m, uint32_t cnt) {
    asm volatile("mbarrier.init.shared.b64 [%0], %1;" :: "r"(m), "r"(cnt) : "memory");
}
__device__ __forceinline__ void mbar_arrive(uint32_t m) {
    asm volatile("mbarrier.arrive.release.cta.shared::cta.b64 _, [%0];" :: "r"(m) : "memory");
}
__device__ __forceinline__ void mbar_wait(uint32_t m, uint32_t parity) {
    asm volatile(
        "{\n\t.reg .pred P;\n\t"
        "W_%=:\n\t"
        "mbarrier.try_wait.parity.acquire.cta.shared::cta.b64 P, [%0], %1, 0x989680;\n\t"
        "@!P bra W_%=;\n\t}"
        :: "r"(m), "r"(parity) : "memory");
}
__device__ __forceinline__ void mma_tf32(float c[4], const uint32_t a[4], const uint32_t b[2]) {
    asm volatile(
        "mma.sync.aligned.m16n8k8.row.col.f32.tf32.tf32.f32 "
        "{%0,%1,%2,%3}, {%4,%5,%6,%7}, {%8,%9}, {%0,%1,%2,%3};"
        : "+f"(c[0]), "+f"(c[1]), "+f"(c[2]), "+f"(c[3])
        : "r"(a[0]), "r"(a[1]), "r"(a[2]), "r"(a[3]), "r"(b[0]), "r"(b[1]));
}

extern "C" __global__ void __launch_bounds__(NTHREADS, 1)
moelb_ws(const float* __restrict__ x,
         const float* __restrict__ W,
         float* __restrict__ out,
         int iters)
{
    extern __shared__ char smem[];
    const uint32_t sb = smem_u32(smem);
    float* Xs = reinterpret_cast<float*>(smem + SM_X);
    float* Ws = reinterpret_cast<float*>(smem + SM_W);

    const int tid  = threadIdx.x;
    const int wid  = tid >> 5;
    const int lane = tid & 31;
    const int g    = lane >> 2;
    const int tig  = lane & 3;
    const int sk   = g << 2;

    const int nOff = blockIdx.x * BN;
    const int e    = blockIdx.y;

    // ---- Prologue: resident W tile [256 x 128], SW swizzle, tf32-rounded ----
    {
        const float4* w4 = reinterpret_cast<const float4*>(W)
                         + ((size_t)e * OUTF + nOff) * (RANK / 4);
        for (int idx = tid; idx < BN * (RANK / 4); idx += NTHREADS) {
            int row = idx >> 5;             // 0..255
            int q   = idx & 31;             // float4 within 128 floats
            float4 v = w4[idx];
            uint4 t = make_uint4(tf32u(v.x), tf32u(v.y), tf32u(v.z), tf32u(v.w));
            uint32_t byte = (uint32_t)row * 512 + (((uint32_t)q * 16) ^ (((uint32_t)row & 7) << 4));
            *reinterpret_cast<uint4*>(smem + SM_W + byte) = t;
        }
    }
    if (tid == 0) {
        mbar_init(sb + SM_FULL0, 64);
        mbar_init(sb + SM_FULL1, 64);
        mbar_init(sb + SM_FREE0, 256);
        mbar_init(sb + SM_FREE1, 256);
    }
    __syncthreads();

    if (wid < 8) {
        // ===================== compute warps: warp tile 64x64 =====================
        const int mW = (wid >> 2) * 64;     // 0 or 64
        const int nW = (wid & 3) * 64;      // 0,64,128,192
        uint32_t phf[2] = {0, 0};
        float acc[4][8][4];

        for (int it = 0; it < iters; ++it) {
            #pragma unroll
            for (int mt = 0; mt < 4; ++mt)
                #pragma unroll
                for (int nt = 0; nt < 8; ++nt)
                    #pragma unroll
                    for (int i = 0; i < 4; ++i)
                        acc[mt][nt][i] = 0.0f;

            #pragma unroll
            for (int ch = 0; ch < 2; ++ch) {
                const int buf = ch;
                mbar_wait(sb + SM_FULL0 + buf * 8, phf[buf]); phf[buf] ^= 1;
                const float* Xb = Xs + buf * 8192;   // 32KB chunk

                #pragma unroll
                for (int ks = 0; ks < 8; ++ks) {
                    const int k0  = ks * 8;
                    const int o1x = ( k0      ^ sk) + tig;       // X chunk-local col
                    const int o2x = ((k0 + 4) ^ sk) + tig;
                    const int kg  = ch * 64 + k0;                // W global k
                    const int o1w = ( kg      ^ sk) + tig;
                    const int o2w = ((kg + 4) ^ sk) + tig;

                    uint32_t a[4][4];
                    #pragma unroll
                    for (int mt = 0; mt < 4; ++mt) {
                        int r0 = mW + mt * 16 + g;
                        a[mt][0] = __float_as_uint(Xb[(r0    ) * 64 + o1x]);
                        a[mt][1] = __float_as_uint(Xb[(r0 + 8) * 64 + o1x]);
                        a[mt][2] = __float_as_uint(Xb[(r0    ) * 64 + o2x]);
                        a[mt][3] = __float_as_uint(Xb[(r0 + 8) * 64 + o2x]);
                    }
                    uint32_t b[8][2];
                    #pragma unroll
                    for (int nt = 0; nt < 8; ++nt) {
                        int n = nW + nt * 8 + g;
                        b[nt][0] = __float_as_uint(Ws[n * RANK + o1w]);
                        b[nt][1] = __float_as_uint(Ws[n * RANK + o2w]);
                    }
                    #pragma unroll
                    for (int mt = 0; mt < 4; ++mt)
                        #pragma unroll
                        for (int nt = 0; nt < 8; ++nt)
                            mma_tf32(acc[mt][nt], a[mt], b[nt]);
                }
                mbar_arrive(sb + SM_FREE0 + buf * 8);
            }

            // ---- epilogue: out[t, e, o] ----
            #pragma unroll
            for (int mt = 0; mt < 4; ++mt) {
                const int t0 = it * BM + mW + mt * 16 + g;
                float* p0 = out + ((size_t)t0 * EXPERTS + e) * OUTF + nOff + nW;
                float* p1 = p0 + (size_t)8 * EXPERTS * OUTF;
                #pragma unroll
                for (int nt = 0; nt < 8; ++nt) {
                    int o = nt * 8 + 2 * tig;
                    *reinterpret_cast<float2*>(p0 + o) =
                        make_float2(acc[mt][nt][0], acc[mt][nt][1]);
                    *reinterpret_cast<float2*>(p1 + o) =
                        make_float2(acc[mt][nt][2], acc[mt][nt][3]);
                }
            }
        }
    } else {
        // ===================== producer warps (wid 8,9) =====================
        const int pw = wid - 8;             // row half: 0 -> rows 0-63, 1 -> 64-127
        const float4* x4 = reinterpret_cast<const float4*>(x);
        uint32_t phr[2] = {0, 0};
        const int nchunks = iters * 2;

        for (int ci = 0; ci < nchunks; ++ci) {
            const int buf = ci & 1;
            if (ci >= 2) { mbar_wait(sb + SM_FREE0 + buf * 8, phr[buf]); phr[buf] ^= 1; }
            const int i = ci >> 1, c = ci & 1;
            const float4* src = x4 + ((size_t)(i * BM + pw * 64)) * 256 + e * 32 + c * 16;
            char* dst = smem + SM_X + buf * 32768 + pw * (64 * 256);

            #pragma unroll 8
            for (int p = 0; p < 32; ++p) {
                int idx = p * 32 + lane;    // 0..1023
                int r   = idx >> 4;         // local row 0..63
                int q   = idx & 15;         // float4 within 64 floats
                float4 v = src[(size_t)r * 256 + q];
                uint4 t = make_uint4(tf32u(v.x), tf32u(v.y), tf32u(v.z), tf32u(v.w));
                uint32_t byte = (uint32_t)r * 256 + (((uint32_t)q * 16) ^ (((uint32_t)r & 7) << 4));
                *reinterpret_cast<uint4*>(dst + byte) = t;
            }
            mbar_arrive(sb + SM_FULL0 + buf * 8);
        }
    }
    __syncthreads();
}

extern "C" void kernel_launch(void* const* d_in, const int* in_sizes, int n_in,
                              void* d_out, int out_size)
{
    const float* x = (const float*)d_in[0];
    const float* W = (const float*)d_in[1];
    float* out = (float*)d_out;

    const int T = in_sizes[0] / (EXPERTS * RANK);
    const int iters = T / BM;

    cudaFuncSetAttribute(moelb_ws,
                         cudaFuncAttributeMaxDynamicSharedMemorySize, SMEM_TOTAL);

    dim3 grid(OUTF / BN, EXPERTS);
    moelb_ws<<<grid, NTHREADS, SMEM_TOTAL>>>(x, W, out, iters);
}

// round 7
// speedup vs baseline: 1.5560x; 1.5560x over previous
#include <cuda_runtime.h>
#include <cstdint>
#include <cstddef>

// out[t,e,o] = sum_r x[t, e*128+r] * W[e,o,r]
// x: [8192, 1024] f32, W: [8, 4096, 128] f32, out: [8192, 8, 4096] f32
//
// mma.sync TF32 (tcgen05 unavailable: harness compiles via compute_103 PTX).
// CTA tile 128(M) x 256(N), full K=128 in smem. 8 warps, warp tile 64x64.
//
// k-slot permutation trick: MMA k-slots (tig, tig+4) of k-step j are fed
// physical k = {8j+2*tig, 8j+2*tig+1} -- a contiguous pair in natural layout,
// so every fragment load is a single LDS.64. Swizzle col ^= 8*(row&7) makes
// half-warp fragment loads cover all 16 8B slots of a 128B line (conflict-free).

#define EXPERTS 8
#define RANK    128
#define OUTF    4096
#define BM      128
#define BN      256

#define SM_X 0
#define SM_W 65536
#define SMEM_TOTAL (65536 + 131072)   // 192KB

__device__ __forceinline__ uint32_t tf32u(float f) {
    uint32_t u;
    asm("cvt.rna.tf32.f32 %0, %1;" : "=r"(u) : "f"(f));
    return u;
}

__device__ __forceinline__ void mma_tf32(float c[4],
                                         uint32_t a0, uint32_t a1, uint32_t a2, uint32_t a3,
                                         uint32_t b0, uint32_t b1) {
    asm volatile(
        "mma.sync.aligned.m16n8k8.row.col.f32.tf32.tf32.f32 "
        "{%0,%1,%2,%3}, {%4,%5,%6,%7}, {%8,%9}, {%0,%1,%2,%3};"
        : "+f"(c[0]), "+f"(c[1]), "+f"(c[2]), "+f"(c[3])
        : "r"(a0), "r"(a1), "r"(a2), "r"(a3), "r"(b0), "r"(b1));
}

extern "C" __global__ void __launch_bounds__(256, 1)
moelb_v4(const float* __restrict__ x,
         const float* __restrict__ W,
         float* __restrict__ out)
{
    extern __shared__ char smem[];
    float* Xs = reinterpret_cast<float*>(smem + SM_X);   // [128][128]
    float* Ws = reinterpret_cast<float*>(smem + SM_W);   // [256][128]

    const int tid  = threadIdx.x;
    const int wid  = tid >> 5;
    const int lane = tid & 31;
    const int g    = lane >> 2;
    const int tig  = lane & 3;

    const int tOff = blockIdx.x * BM;
    const int nOff = blockIdx.y * BN;
    const int e    = blockIdx.z;

    // ---- Load X tile [128 x 128] (tf32-rounded, swizzled: col ^= 8*(row&7)) ----
    {
        const float4* x4 = reinterpret_cast<const float4*>(x);
        #pragma unroll
        for (int p = 0; p < 16; ++p) {
            int idx = p * 256 + tid;
            int row = idx >> 5;              // 0..127
            int q   = idx & 31;              // float4 slot in row
            float4 v = x4[(size_t)(tOff + row) * 256 + e * 32 + q];
            uint4 t = make_uint4(tf32u(v.x), tf32u(v.y), tf32u(v.z), tf32u(v.w));
            uint32_t byte = (uint32_t)row * 512 + (((uint32_t)q * 16) ^ (((uint32_t)row & 7) << 5));
            *reinterpret_cast<uint4*>(smem + SM_X + byte) = t;
        }
    }
    // ---- Load W tile [256 x 128] (contiguous block, same swizzle) ----
    {
        const float4* w4 = reinterpret_cast<const float4*>(W)
                         + ((size_t)e * OUTF + nOff) * (RANK / 4);
        #pragma unroll
        for (int p = 0; p < 32; ++p) {
            int idx = p * 256 + tid;
            int row = idx >> 5;              // 0..255
            int q   = idx & 31;
            float4 v = w4[idx];
            uint4 t = make_uint4(tf32u(v.x), tf32u(v.y), tf32u(v.z), tf32u(v.w));
            uint32_t byte = (uint32_t)row * 512 + (((uint32_t)q * 16) ^ (((uint32_t)row & 7) << 5));
            *reinterpret_cast<uint4*>(smem + SM_W + byte) = t;
        }
    }
    __syncthreads();

    // ---- Mainloop: warp tile 64x64, 16 k-steps ----
    const int mW  = (wid >> 2) * 64;      // 0 or 64
    const int nW  = (wid & 3) * 64;       // 0,64,128,192
    const int skf = g << 3;               // swizzle XOR (float units)
    const int t2  = tig << 1;

    // hoisted row bases (float index)
    int aRow[4][2], bRow[8];
    #pragma unroll
    for (int mt = 0; mt < 4; ++mt) {
        aRow[mt][0] = (mW + mt * 16 + g) * RANK;
        aRow[mt][1] = (mW + mt * 16 + 8 + g) * RANK;
    }
    #pragma unroll
    for (int nt = 0; nt < 8; ++nt)
        bRow[nt] = (nW + nt * 8 + g) * RANK;

    float acc[4][8][4];
    #pragma unroll
    for (int mt = 0; mt < 4; ++mt)
        #pragma unroll
        for (int nt = 0; nt < 8; ++nt)
            #pragma unroll
            for (int i = 0; i < 4; ++i)
                acc[mt][nt][i] = 0.0f;

    float2 Af[2][4][2];
    float2 Bf[2][8];

    // prologue: load k-step 0 fragments
    {
        const int o = ((0 << 3) ^ skf) + t2;
        #pragma unroll
        for (int mt = 0; mt < 4; ++mt) {
            Af[0][mt][0] = *reinterpret_cast<const float2*>(&Xs[aRow[mt][0] + o]);
            Af[0][mt][1] = *reinterpret_cast<const float2*>(&Xs[aRow[mt][1] + o]);
        }
        #pragma unroll
        for (int nt = 0; nt < 8; ++nt)
            Bf[0][nt] = *reinterpret_cast<const float2*>(&Ws[bRow[nt] + o]);
    }

    #pragma unroll
    for (int j = 0; j < 16; ++j) {
        const int s = j & 1;
        if (j < 15) {
            const int o = (((j + 1) << 3) ^ skf) + t2;
            const int n = s ^ 1;
            #pragma unroll
            for (int mt = 0; mt < 4; ++mt) {
                Af[n][mt][0] = *reinterpret_cast<const float2*>(&Xs[aRow[mt][0] + o]);
                Af[n][mt][1] = *reinterpret_cast<const float2*>(&Xs[aRow[mt][1] + o]);
            }
            #pragma unroll
            for (int nt = 0; nt < 8; ++nt)
                Bf[n][nt] = *reinterpret_cast<const float2*>(&Ws[bRow[nt] + o]);
        }
        #pragma unroll
        for (int mt = 0; mt < 4; ++mt) {
            uint32_t a0 = __float_as_uint(Af[s][mt][0].x);
            uint32_t a1 = __float_as_uint(Af[s][mt][1].x);
            uint32_t a2 = __float_as_uint(Af[s][mt][0].y);
            uint32_t a3 = __float_as_uint(Af[s][mt][1].y);
            #pragma unroll
            for (int nt = 0; nt < 8; ++nt)
                mma_tf32(acc[mt][nt], a0, a1, a2, a3,
                         __float_as_uint(Bf[s][nt].x), __float_as_uint(Bf[s][nt].y));
        }
    }

    // ---- Epilogue: out[t, e, o] ----
    #pragma unroll
    for (int mt = 0; mt < 4; ++mt) {
        const int t0 = tOff + mW + mt * 16 + g;
        float* p0 = out + ((size_t)t0 * EXPERTS + e) * OUTF + nOff + nW;
        float* p1 = p0 + (size_t)8 * EXPERTS * OUTF;
        #pragma unroll
        for (int nt = 0; nt < 8; ++nt) {
            int o = nt * 8 + 2 * tig;
            *reinterpret_cast<float2*>(p0 + o) = make_float2(acc[mt][nt][0], acc[mt][nt][1]);
            *reinterpret_cast<float2*>(p1 + o) = make_float2(acc[mt][nt][2], acc[mt][nt][3]);
        }
    }
}

extern "C" void kernel_launch(void* const* d_in, const int* in_sizes, int n_in,
                              void* d_out, int out_size)
{
    const float* x = (const float*)d_in[0];
    const float* W = (const float*)d_in[1];
    float* out = (float*)d_out;

    const int T = in_sizes[0] / (EXPERTS * RANK);

    cudaFuncSetAttribute(moelb_v4,
                         cudaFuncAttributeMaxDynamicSharedMemorySize, SMEM_TOTAL);

    dim3 grid(T / BM, OUTF / BN, EXPERTS);
    moelb_v4<<<grid, 256, SMEM_TOTAL>>>(x, W, out);
}

// round 8
// speedup vs baseline: 1.6877x; 1.0847x over previous
#include <cuda_runtime.h>
#include <cstdint>
#include <cstddef>

// out[t,e,o] = sum_r x[t, e*128+r] * W[e,o,r]
// x: [8192, 1024] f32, W: [8, 4096, 128] f32, out: [8192, 8, 4096] f32
//
// mma.sync TF32 (tcgen05 unavailable: harness compiles via compute_103 PTX).
// Round 8: operands pre-rounded to TF32 by two streaming kernels into
// __device__ scratch; main kernel loads tiles with cp.async.cg in a 2-stage
// k-pipeline (k[0:64] / k[64:128]) so the tile load overlaps the mainloop.
// Mainloop = R7's LDS.64 k-slot-permutation scheme (warp tile 64x64).

#define EXPERTS 8
#define RANK    128
#define OUTF    4096
#define TOKENS  8192
#define BM      128
#define BN      256

#define SM_X 0
#define SM_W 65536
#define SMEM_TOTAL (65536 + 131072)   // 192KB

__device__ float g_Xr[(size_t)TOKENS * EXPERTS * RANK];   // 32MB tf32-rounded x
__device__ float g_Wr[(size_t)EXPERTS * OUTF * RANK];     // 16MB tf32-rounded W

__device__ __forceinline__ uint32_t tf32u(float f) {
    uint32_t u;
    asm("cvt.rna.tf32.f32 %0, %1;" : "=r"(u) : "f"(f));
    return u;
}
__device__ __forceinline__ uint32_t smem_u32(const void* p) {
    uint32_t a;
    asm("{ .reg .u64 t; cvta.to.shared.u64 t, %1; cvt.u32.u64 %0, t; }" : "=r"(a) : "l"(p));
    return a;
}
__device__ __forceinline__ void cp16(uint32_t dst, const void* src) {
    asm volatile("cp.async.cg.shared.global [%0], [%1], 16;" :: "r"(dst), "l"(src) : "memory");
}
__device__ __forceinline__ void mma_tf32(float c[4],
                                         uint32_t a0, uint32_t a1, uint32_t a2, uint32_t a3,
                                         uint32_t b0, uint32_t b1) {
    asm volatile(
        "mma.sync.aligned.m16n8k8.row.col.f32.tf32.tf32.f32 "
        "{%0,%1,%2,%3}, {%4,%5,%6,%7}, {%8,%9}, {%0,%1,%2,%3};"
        : "+f"(c[0]), "+f"(c[1]), "+f"(c[2]), "+f"(c[3])
        : "r"(a0), "r"(a1), "r"(a2), "r"(a3), "r"(b0), "r"(b1));
}

// ---- streaming pre-round kernels ----
__global__ void __launch_bounds__(1024, 2) round_x(const float4* __restrict__ src, int n4) {
    int i = blockIdx.x * blockDim.x + threadIdx.x;
    if (i < n4) {
        float4 v = src[i];
        reinterpret_cast<uint4*>(g_Xr)[i] =
            make_uint4(tf32u(v.x), tf32u(v.y), tf32u(v.z), tf32u(v.w));
    }
}
__global__ void __launch_bounds__(1024, 2) round_w(const float4* __restrict__ src, int n4) {
    int i = blockIdx.x * blockDim.x + threadIdx.x;
    if (i < n4) {
        float4 v = src[i];
        reinterpret_cast<uint4*>(g_Wr)[i] =
            make_uint4(tf32u(v.x), tf32u(v.y), tf32u(v.z), tf32u(v.w));
    }
}

extern "C" __global__ void __launch_bounds__(256, 1)
moelb_v5(float* __restrict__ out)
{
    extern __shared__ char smem[];
    const uint32_t sb = smem_u32(smem);
    float* Xs = reinterpret_cast<float*>(smem + SM_X);   // [128][128] swizzled
    float* Ws = reinterpret_cast<float*>(smem + SM_W);   // [256][128] swizzled

    const int tid  = threadIdx.x;
    const int wid  = tid >> 5;
    const int lane = tid & 31;
    const int g    = lane >> 2;
    const int tig  = lane & 3;

    const int tOff = blockIdx.x * BM;
    const int nOff = blockIdx.y * BN;
    const int e    = blockIdx.z;

    // ---- issue both k-stages with cp.async (stage s covers float4 slots q = s*16..s*16+15) ----
    const float* xsrc = g_Xr + (size_t)tOff * (EXPERTS * RANK) + e * RANK;
    const float* wsrc = g_Wr + ((size_t)e * OUTF + nOff) * RANK;

    #pragma unroll
    for (int s = 0; s < 2; ++s) {
        #pragma unroll
        for (int p = 0; p < 8; ++p) {                     // X: 128 rows x 16 q
            int idx = p * 256 + tid;
            int row = idx >> 4, q = s * 16 + (idx & 15);
            uint32_t dst = sb + SM_X + (uint32_t)row * 512
                         + (((uint32_t)q * 16) ^ (((uint32_t)row & 7) << 5));
            cp16(dst, xsrc + (size_t)row * (EXPERTS * RANK) + q * 4);
        }
        #pragma unroll
        for (int p = 0; p < 16; ++p) {                    // W: 256 rows x 16 q
            int idx = p * 256 + tid;
            int row = idx >> 4, q = s * 16 + (idx & 15);
            uint32_t dst = sb + SM_W + (uint32_t)row * 512
                         + (((uint32_t)q * 16) ^ (((uint32_t)row & 7) << 5));
            cp16(dst, wsrc + (size_t)row * RANK + q * 4);
        }
        asm volatile("cp.async.commit_group;" ::: "memory");
    }

    // ---- mainloop setup: warp tile 64x64, LDS.64 fragments ----
    const int mW  = (wid >> 2) * 64;
    const int nW  = (wid & 3) * 64;
    const int skf = g << 3;
    const int t2  = tig << 1;

    int aRow[4][2], bRow[8];
    #pragma unroll
    for (int mt = 0; mt < 4; ++mt) {
        aRow[mt][0] = (mW + mt * 16 + g) * RANK;
        aRow[mt][1] = (mW + mt * 16 + 8 + g) * RANK;
    }
    #pragma unroll
    for (int nt = 0; nt < 8; ++nt)
        bRow[nt] = (nW + nt * 8 + g) * RANK;

    float acc[4][8][4];
    #pragma unroll
    for (int mt = 0; mt < 4; ++mt)
        #pragma unroll
        for (int nt = 0; nt < 8; ++nt)
            #pragma unroll
            for (int i = 0; i < 4; ++i)
                acc[mt][nt][i] = 0.0f;

    float2 Af[2][4][2];
    float2 Bf[2][8];

    #pragma unroll
    for (int half = 0; half < 2; ++half) {
        if (half == 0) asm volatile("cp.async.wait_group 1;" ::: "memory");
        else           asm volatile("cp.async.wait_group 0;" ::: "memory");
        __syncthreads();

        // prologue: fragments for first k-step of this half
        {
            const int o = (((half * 8) << 3) ^ skf) + t2;
            #pragma unroll
            for (int mt = 0; mt < 4; ++mt) {
                Af[0][mt][0] = *reinterpret_cast<const float2*>(&Xs[aRow[mt][0] + o]);
                Af[0][mt][1] = *reinterpret_cast<const float2*>(&Xs[aRow[mt][1] + o]);
            }
            #pragma unroll
            for (int nt = 0; nt < 8; ++nt)
                Bf[0][nt] = *reinterpret_cast<const float2*>(&Ws[bRow[nt] + o]);
        }

        #pragma unroll
        for (int jj = 0; jj < 8; ++jj) {
            const int s = jj & 1;
            if (jj < 7) {
                const int o = (((half * 8 + jj + 1) << 3) ^ skf) + t2;
                const int n = s ^ 1;
                #pragma unroll
                for (int mt = 0; mt < 4; ++mt) {
                    Af[n][mt][0] = *reinterpret_cast<const float2*>(&Xs[aRow[mt][0] + o]);
                    Af[n][mt][1] = *reinterpret_cast<const float2*>(&Xs[aRow[mt][1] + o]);
                }
                #pragma unroll
                for (int nt = 0; nt < 8; ++nt)
                    Bf[n][nt] = *reinterpret_cast<const float2*>(&Ws[bRow[nt] + o]);
            }
            #pragma unroll
            for (int mt = 0; mt < 4; ++mt) {
                uint32_t a0 = __float_as_uint(Af[s][mt][0].x);
                uint32_t a1 = __float_as_uint(Af[s][mt][1].x);
                uint32_t a2 = __float_as_uint(Af[s][mt][0].y);
                uint32_t a3 = __float_as_uint(Af[s][mt][1].y);
                #pragma unroll
                for (int nt = 0; nt < 8; ++nt)
                    mma_tf32(acc[mt][nt], a0, a1, a2, a3,
                             __float_as_uint(Bf[s][nt].x), __float_as_uint(Bf[s][nt].y));
            }
        }
    }

    // ---- epilogue: out[t, e, o] ----
    #pragma unroll
    for (int mt = 0; mt < 4; ++mt) {
        const int t0 = tOff + mW + mt * 16 + g;
        float* p0 = out + ((size_t)t0 * EXPERTS + e) * OUTF + nOff + nW;
        float* p1 = p0 + (size_t)8 * EXPERTS * OUTF;
        #pragma unroll
        for (int nt = 0; nt < 8; ++nt) {
            int o = nt * 8 + 2 * tig;
            *reinterpret_cast<float2*>(p0 + o) = make_float2(acc[mt][nt][0], acc[mt][nt][1]);
            *reinterpret_cast<float2*>(p1 + o) = make_float2(acc[mt][nt][2], acc[mt][nt][3]);
        }
    }
}

extern "C" void kernel_launch(void* const* d_in, const int* in_sizes, int n_in,
                              void* d_out, int out_size)
{
    const float* x = (const float*)d_in[0];
    const float* W = (const float*)d_in[1];
    float* out = (float*)d_out;

    const int T = in_sizes[0] / (EXPERTS * RANK);

    // pre-round operands to TF32
    const int nx4 = in_sizes[0] / 4;
    const int nw4 = in_sizes[1] / 4;
    round_x<<<(nx4 + 1023) / 1024, 1024>>>((const float4*)x, nx4);
    round_w<<<(nw4 + 1023) / 1024, 1024>>>((const float4*)W, nw4);

    cudaFuncSetAttribute(moelb_v5,
                         cudaFuncAttributeMaxDynamicSharedMemorySize, SMEM_TOTAL);

    dim3 grid(T / BM, OUTF / BN, EXPERTS);
    moelb_v5<<<grid, 256, SMEM_TOTAL>>>(out);
}